// round 1
// baseline (speedup 1.0000x reference)
#include <cuda_runtime.h>
#include <math.h>

#define NNODE   128
#define DDIM    256
#define TT      512
#define MSTRIDE 132          // 128 + 4 padding, float4-aligned
#define THREADS 256
#define XSTRIDE 68           // x chunk stride (64 + 4)

// smem layout (floats):
//   sA   : 128*132   adjacency
//   sS   : 128*132   normA -> S
//   sQ   : 128*132   x-chunk staging, then Q = S^T adj
//   sw   : 256       lin_w
//   s_s  : 128       x @ w
//   s_al : 128       alpha
//   s_ca : 128       cut_alpha
//   s_di : 128       deg^-1/2
//   s_rs : 128       adj row sums
//   flags: 128 (int), cut (float), nuniq (int)
#define SMEM_FLOATS (3*128*MSTRIDE + 256 + 5*128 + 132)
#define SMEM_BYTES  (SMEM_FLOATS * 4)

__global__ __launch_bounds__(THREADS, 1)
void graph_enc_kernel(const float* __restrict__ x,     // [B,128,256]
                      const float* __restrict__ adj,   // [B,128,128]
                      const int*   __restrict__ head,  // [B,512]
                      const float* __restrict__ linw,  // [256]
                      const float* __restrict__ bias,  // [1]
                      float* __restrict__ out_emb,     // [B,128,256]
                      float* __restrict__ out_adj)     // [B,128,128]
{
    extern __shared__ float sm[];
    float* sA    = sm;
    float* sS    = sA + 128*MSTRIDE;
    float* sQ    = sS + 128*MSTRIDE;
    float* sw    = sQ + 128*MSTRIDE;
    float* s_s   = sw + 256;
    float* s_al  = s_s + 128;
    float* s_ca  = s_al + 128;
    float* s_di  = s_ca + 128;
    float* s_rs  = s_di + 128;
    int*   s_fl  = (int*)(s_rs + 128);
    float* s_cut = (float*)(s_fl + 128);
    int*   s_nu  = (int*)(s_cut + 1);

    const int tid  = threadIdx.x;
    const int b    = blockIdx.x;
    const int lane = tid & 31;
    const int wrp  = tid >> 5;

    const float* xB   = x   + (size_t)b * NNODE * DDIM;
    const float* adjB = adj + (size_t)b * NNODE * NNODE;

    // ---- Phase 0: init + load ----
    sw[tid] = linw[tid];                 // 256 threads == D
    if (tid < 128) s_fl[tid] = 0;
    if (tid == 0) { *s_nu = 0; *s_cut = 0.0f; }

    // adj -> sA (float4, 4096 vec loads)
    for (int t = tid; t < 4096; t += THREADS) {
        int i = t >> 5;
        int f = t & 31;
        reinterpret_cast<float4*>(&sA[i * MSTRIDE])[f] =
            reinterpret_cast<const float4*>(adjB)[t];
    }
    __syncthreads();

    // head flags (after flags zeroed)
    for (int t = tid; t < TT; t += THREADS) {
        int h = head[(size_t)b * TT + t];
        s_fl[h] = 1;
    }

    // ---- Phase 1: row sums, s = x@w, deg^-1/2 (warp per row) ----
    for (int i = wrp; i < 128; i += 8) {
        const float* row = &sA[i * MSTRIDE];
        float rs = row[lane] + row[lane + 32] + row[lane + 64] + row[lane + 96];
        #pragma unroll
        for (int o = 16; o; o >>= 1) rs += __shfl_xor_sync(0xFFFFFFFFu, rs, o);

        const float* xr = xB + i * DDIM;
        float dot = 0.0f;
        #pragma unroll
        for (int q = 0; q < 8; ++q) dot = fmaf(xr[lane + q*32], sw[lane + q*32], dot);
        #pragma unroll
        for (int o = 16; o; o >>= 1) dot += __shfl_xor_sync(0xFFFFFFFFu, dot, o);

        if (lane == 0) {
            s_rs[i] = rs;
            s_s[i]  = dot;
            float deg = rs + 1.0f;           // row sum of (adj + I)
            if (deg < 1.0f) deg = 1.0f;      // clip(.,1)
            s_di[i] = rsqrtf(deg);
        }
    }
    __syncthreads();

    // ---- Phase 2: normA into sS, out2 = normA@s + bias, alpha ----
    const float biasv = bias[0];
    for (int i = wrp; i < 128; i += 8) {
        const float mask = (s_rs[i] > 0.0f) ? 1.0f : 0.0f;
        const float di   = s_di[i] * mask;
        float acc = 0.0f;
        #pragma unroll
        for (int q = 0; q < 4; ++q) {
            int j = lane + q * 32;
            float v = (sA[i * MSTRIDE + j] + ((j == i) ? 1.0f : 0.0f)) * di * s_di[j];
            sS[i * MSTRIDE + j] = v;
            acc = fmaf(v, s_s[j], acc);
        }
        #pragma unroll
        for (int o = 16; o; o >>= 1) acc += __shfl_xor_sync(0xFFFFFFFFu, acc, o);
        if (lane == 0) {
            float o2 = acc + biasv;
            float z  = o2 * o2;
            s_al[i]  = 1.0f / (1.0f + expf(-z));
        }
    }
    __syncthreads();

    // ---- Phase 3: unique count, k, cut ----
    if (tid < 128) atomicAdd(s_nu, s_fl[tid]);
    __syncthreads();
    const int nuniq = *s_nu;
    int kidx = (int)ceilf((float)nuniq * 0.1f) + 1 - 1;   // k - 1
    if (kidx < 0) kidx = 0;
    if (kidx > 127) kidx = 127;
    if (nuniq > 1 && tid < 128) {
        const float ai = s_al[tid];
        int r = 0;
        #pragma unroll 4
        for (int j = 0; j < 128; ++j) {
            float aj = s_al[j];
            r += (aj > ai) || (aj == ai && j < tid);
        }
        if (r == kidx) *s_cut = ai;   // unique writer (ranks are a permutation)
    }
    __syncthreads();
    const float cut = *s_cut;
    if (tid < 128) s_ca[tid] = fmaxf(s_al[tid] + 1e-7f - cut, 0.0f);
    __syncthreads();

    // ---- Phase 4: S = rowL1norm(normA * ca_col) in place ----
    for (int i = wrp; i < 128; i += 8) {
        float acc = 0.0f;
        #pragma unroll
        for (int q = 0; q < 4; ++q) {
            int j = lane + q * 32;
            acc = fmaf(sS[i * MSTRIDE + j], s_ca[j], acc);   // all terms >= 0
        }
        #pragma unroll
        for (int o = 16; o; o >>= 1) acc += __shfl_xor_sync(0xFFFFFFFFu, acc, o);
        const float inv = 1.0f / fmaxf(acc, 1e-12f);
        #pragma unroll
        for (int q = 0; q < 4; ++q) {
            int j = lane + q * 32;
            sS[i * MSTRIDE + j] = sS[i * MSTRIDE + j] * s_ca[j] * inv;
        }
    }
    __syncthreads();

    // ---- GEMM1: emb = S^T @ x  (128 x 256), d-chunks of 64 staged in sQ ----
    {
        const int tcol = tid & 15;           // d group
        const int trow = tid >> 4;           // j group
        const int j0 = trow * 8;
        const int d0 = tcol * 4;
        float* outB = out_emb + (size_t)b * NNODE * DDIM;

        for (int c = 0; c < 4; ++c) {
            __syncthreads();   // previous chunk's sQ reads done
            for (int t = tid; t < 2048; t += THREADS) {
                int i = t >> 4;
                int f = t & 15;
                reinterpret_cast<float4*>(&sQ[i * XSTRIDE])[f] =
                    reinterpret_cast<const float4*>(xB + i * DDIM + c * 64)[f];
            }
            __syncthreads();

            float acc[8][4];
            #pragma unroll
            for (int u = 0; u < 8; ++u)
                #pragma unroll
                for (int v = 0; v < 4; ++v) acc[u][v] = 0.0f;

            #pragma unroll 2
            for (int i = 0; i < 128; ++i) {
                const float4 a0 = *reinterpret_cast<const float4*>(&sS[i * MSTRIDE + j0]);
                const float4 a1 = *reinterpret_cast<const float4*>(&sS[i * MSTRIDE + j0 + 4]);
                const float4 bv = *reinterpret_cast<const float4*>(&sQ[i * XSTRIDE + d0]);
                const float av[8] = {a0.x, a0.y, a0.z, a0.w, a1.x, a1.y, a1.z, a1.w};
                const float bb[4] = {bv.x, bv.y, bv.z, bv.w};
                #pragma unroll
                for (int u = 0; u < 8; ++u)
                    #pragma unroll
                    for (int v = 0; v < 4; ++v)
                        acc[u][v] = fmaf(av[u], bb[v], acc[u][v]);
            }
            #pragma unroll
            for (int u = 0; u < 8; ++u) {
                float4 o = make_float4(acc[u][0], acc[u][1], acc[u][2], acc[u][3]);
                *reinterpret_cast<float4*>(&outB[(size_t)(j0 + u) * DDIM + c * 64 + d0]) = o;
            }
        }
    }
    __syncthreads();   // all sQ (x-chunk) reads complete before Q overwrite

    // ---- GEMM2: Q = S^T @ adj  (128 x 128) -> sQ ----
    {
        const int t2c = tid & 15;
        const int t2r = tid >> 4;
        const int j0 = t2r * 8;
        const int m0 = t2c * 8;
        float acc[8][8];
        #pragma unroll
        for (int u = 0; u < 8; ++u)
            #pragma unroll
            for (int v = 0; v < 8; ++v) acc[u][v] = 0.0f;

        #pragma unroll 2
        for (int i = 0; i < 128; ++i) {
            const float4 a0 = *reinterpret_cast<const float4*>(&sS[i * MSTRIDE + j0]);
            const float4 a1 = *reinterpret_cast<const float4*>(&sS[i * MSTRIDE + j0 + 4]);
            const float4 b0 = *reinterpret_cast<const float4*>(&sA[i * MSTRIDE + m0]);
            const float4 b1 = *reinterpret_cast<const float4*>(&sA[i * MSTRIDE + m0 + 4]);
            const float av[8] = {a0.x, a0.y, a0.z, a0.w, a1.x, a1.y, a1.z, a1.w};
            const float bb[8] = {b0.x, b0.y, b0.z, b0.w, b1.x, b1.y, b1.z, b1.w};
            #pragma unroll
            for (int u = 0; u < 8; ++u)
                #pragma unroll
                for (int v = 0; v < 8; ++v)
                    acc[u][v] = fmaf(av[u], bb[v], acc[u][v]);
        }
        #pragma unroll
        for (int u = 0; u < 8; ++u) {
            *reinterpret_cast<float4*>(&sQ[(j0 + u) * MSTRIDE + m0]) =
                make_float4(acc[u][0], acc[u][1], acc[u][2], acc[u][3]);
            *reinterpret_cast<float4*>(&sQ[(j0 + u) * MSTRIDE + m0 + 4]) =
                make_float4(acc[u][4], acc[u][5], acc[u][6], acc[u][7]);
        }
    }
    __syncthreads();

    // ---- GEMM3: new_adj = Q @ S  (128 x 128) ----
    {
        const int t2c = tid & 15;
        const int t2r = tid >> 4;
        const int j0 = t2r * 8;
        const int l0 = t2c * 8;
        float acc[8][8];
        #pragma unroll
        for (int u = 0; u < 8; ++u)
            #pragma unroll
            for (int v = 0; v < 8; ++v) acc[u][v] = 0.0f;

        #pragma unroll 2
        for (int m = 0; m < 128; ++m) {
            const float4 b0 = *reinterpret_cast<const float4*>(&sS[m * MSTRIDE + l0]);
            const float4 b1 = *reinterpret_cast<const float4*>(&sS[m * MSTRIDE + l0 + 4]);
            const float bb[8] = {b0.x, b0.y, b0.z, b0.w, b1.x, b1.y, b1.z, b1.w};
            float av[8];
            #pragma unroll
            for (int u = 0; u < 8; ++u) av[u] = sQ[(j0 + u) * MSTRIDE + m];
            #pragma unroll
            for (int u = 0; u < 8; ++u)
                #pragma unroll
                for (int v = 0; v < 8; ++v)
                    acc[u][v] = fmaf(av[u], bb[v], acc[u][v]);
        }
        float* oB = out_adj + (size_t)b * NNODE * NNODE;
        #pragma unroll
        for (int u = 0; u < 8; ++u) {
            *reinterpret_cast<float4*>(&oB[(size_t)(j0 + u) * NNODE + l0]) =
                make_float4(acc[u][0], acc[u][1], acc[u][2], acc[u][3]);
            *reinterpret_cast<float4*>(&oB[(size_t)(j0 + u) * NNODE + l0 + 4]) =
                make_float4(acc[u][4], acc[u][5], acc[u][6], acc[u][7]);
        }
    }
}

extern "C" void kernel_launch(void* const* d_in, const int* in_sizes, int n_in,
                              void* d_out, int out_size)
{
    const float* x    = (const float*)d_in[0];   // [B,128,256]
    const float* adj  = (const float*)d_in[1];   // [B,128,128]
    const int*   head = (const int*)  d_in[2];   // [B,512]
    const float* lw   = (const float*)d_in[3];   // [1,256]
    const float* bs   = (const float*)d_in[4];   // [1]

    const int B = in_sizes[0] / (NNODE * DDIM);  // 512

    float* out_emb = (float*)d_out;                              // [B,128,256]
    float* out_adj = out_emb + (size_t)B * NNODE * DDIM;         // [B,128,128]

    cudaFuncSetAttribute(graph_enc_kernel,
                         cudaFuncAttributeMaxDynamicSharedMemorySize, SMEM_BYTES);
    graph_enc_kernel<<<B, THREADS, SMEM_BYTES>>>(x, adj, head, lw, bs, out_emb, out_adj);
}

// round 2
// speedup vs baseline: 2.4700x; 2.4700x over previous
#include <cuda_runtime.h>
#include <math.h>

#define NN   128          // nodes
#define DD   256          // feature dim
#define TTH  512          // head length
#define AST  132          // adj smem stride (floats)
#define SST  20           // active-S smem stride (CH + 4)
#define CH   16           // active-column chunk
#define THREADS 256

// smem floats: adj + Sa + Sb + Q + w + 8 scalar arrays + flags + act + misc
#define SMEM_FLOATS (NN*AST + 2*NN*SST + CH*AST + DD + 8*NN + NN + NN + 8)
#define SMEM_BYTES  (SMEM_FLOATS * 4)

__global__ __launch_bounds__(THREADS, 2)
void graph_enc_kernel(const float* __restrict__ x,     // [B,128,256]
                      const float* __restrict__ adj,   // [B,128,128]
                      const int*   __restrict__ head,  // [B,512]
                      const float* __restrict__ linw,  // [256]
                      const float* __restrict__ bias,  // [1]
                      float* __restrict__ out_emb,     // [B,128,256]
                      float* __restrict__ out_adj)     // [B,128,128]
{
    extern __shared__ float sm[];
    float* sA   = sm;                    // adj [128][132]
    float* sSa  = sA  + NN*AST;          // active S cols, row-chunk [128][20]
    float* sSb  = sSa + NN*SST;          // active S cols, col-chunk [128][20]
    float* sQ   = sSb + NN*SST;          // Qa = S_a^T adj  [16][132]
    float* sw   = sQ  + CH*AST;          // lin_w [256]
    float* s_s  = sw  + DD;              // x @ w
    float* s_di = s_s + NN;              // deg^-1/2
    float* s_md = s_di+ NN;              // mask * di
    float* s_t  = s_md+ NN;              // di * s
    float* s_al = s_t + NN;              // alpha
    float* s_ca = s_al+ NN;              // cut_alpha
    float* s_iv = s_ca+ NN;              // 1/rowL1
    float* s_rs = s_iv+ NN;              // adj row sums
    int*   s_fl = (int*)(s_rs + NN);     // head flags
    int*   s_ac = s_fl + NN;             // active column indices
    int*   s_cn = s_ac + NN;             // active count
    float* s_ct = (float*)(s_cn + 1);    // cut value

    const int tid  = threadIdx.x;
    const int bat  = blockIdx.x;
    const int lane = tid & 31;
    const int wrp  = tid >> 5;

    const float* xB = x   + (size_t)bat * NN * DD;
    const float* aB = adj + (size_t)bat * NN * NN;
    float* oE = out_emb + (size_t)bat * NN * DD;
    float* oA = out_adj + (size_t)bat * NN * NN;

    // ---- P0: init + load adj ----
    sw[tid] = linw[tid];
    if (tid < NN) s_fl[tid] = 0;
    if (tid == 0) { *s_cn = 0; *s_ct = 0.0f; }

    for (int t = tid; t < NN*NN/4; t += THREADS) {
        int i = t >> 5, f = t & 31;
        reinterpret_cast<float4*>(&sA[i * AST])[f] =
            reinterpret_cast<const float4*>(aB)[t];
    }
    __syncthreads();
    for (int t = tid; t < TTH; t += THREADS) s_fl[head[(size_t)bat*TTH + t]] = 1;

    // ---- P1: row sums, s = x@w, di, mask*di (warp per row) ----
    for (int i = wrp; i < NN; i += 8) {
        const float* row = &sA[i * AST];
        float rs = row[lane] + row[lane+32] + row[lane+64] + row[lane+96];
        const float* xr = xB + (size_t)i * DD;
        float dot = 0.0f;
        #pragma unroll
        for (int q = 0; q < 8; ++q) dot = fmaf(xr[lane + q*32], sw[lane + q*32], dot);
        #pragma unroll
        for (int o = 16; o; o >>= 1) {
            rs  += __shfl_xor_sync(0xFFFFFFFFu, rs,  o);
            dot += __shfl_xor_sync(0xFFFFFFFFu, dot, o);
        }
        if (lane == 0) {
            s_rs[i] = rs; s_s[i] = dot;
            float dg = rs + 1.0f; if (dg < 1.0f) dg = 1.0f;
            float di = rsqrtf(dg);
            s_di[i] = di;
            s_md[i] = (rs > 0.0f) ? di : 0.0f;
        }
    }
    __syncthreads();
    if (tid < NN) s_t[tid] = s_di[tid] * s_s[tid];
    __syncthreads();

    // ---- P2: alpha = sigmoid((normA@s + bias)^2) via adj@t ----
    const float bv = bias[0];
    for (int i = wrp; i < NN; i += 8) {
        float acc = 0.0f;
        #pragma unroll
        for (int q = 0; q < 4; ++q) {
            int j = lane + q*32;
            acc = fmaf(sA[i*AST + j], s_t[j], acc);
        }
        #pragma unroll
        for (int o = 16; o; o >>= 1) acc += __shfl_xor_sync(0xFFFFFFFFu, acc, o);
        if (lane == 0) {
            float o2 = s_md[i] * (acc + s_di[i] * s_s[i]) + bv;
            float z  = o2 * o2;
            s_al[i]  = 1.0f / (1.0f + expf(-z));
        }
    }

    // ---- P3: unique count, cut via exact rank select ----
    int nu = __syncthreads_count(tid < NN && s_fl[tid]);
    int kidx = (int)ceilf((float)nu * 0.1f);     // k-1 = ceil(n*0.1)
    if (kidx < 0) kidx = 0;
    if (kidx > NN-1) kidx = NN-1;
    if (nu > 1 && tid < NN) {
        const float ai = s_al[tid];
        int r = 0;
        #pragma unroll 4
        for (int j = 0; j < NN; ++j) {
            float aj = s_al[j];
            r += (aj > ai) || (aj == ai && j < tid);
        }
        if (r == kidx) *s_ct = ai;
    }
    __syncthreads();
    const float cut = *s_ct;

    // ---- P4: cut_alpha + active compaction ----
    int pos = -1;
    if (tid < NN) {
        float cav = fmaxf(s_al[tid] + 1e-7f - cut, 0.0f);
        s_ca[tid] = cav;
        if (cav > 0.0f) pos = atomicAdd(s_cn, 1);
    }
    if (pos >= 0) s_ac[pos] = tid;
    __syncthreads();
    const int K = *s_cn;

    // ---- P5: row L1 inverse over ACTIVE columns only ----
    if (tid < NN) {
        const int i = tid;
        float r = 0.0f;
        for (int a = 0; a < K; ++a) {
            int ja = s_ac[a];
            float v = sA[i*AST + ja] + ((i == ja) ? 1.0f : 0.0f);
            r = fmaf(v, s_di[ja] * s_ca[ja], r);
        }
        r *= s_md[i];
        s_iv[i] = 1.0f / fmaxf(r, 1e-12f);
    }
    __syncthreads();

    // ---- zero-fill: all of out_adj; inactive rows of out_emb ----
    const float4 z4 = make_float4(0.f, 0.f, 0.f, 0.f);
    for (int j = wrp; j < NN; j += 8) {
        reinterpret_cast<float4*>(oA + (size_t)j * NN)[lane] = z4;
        if (s_ca[j] == 0.0f) {
            reinterpret_cast<float4*>(oE + (size_t)j * DD)[lane]      = z4;
            reinterpret_cast<float4*>(oE + (size_t)j * DD)[lane + 32] = z4;
        }
    }

    // ---- chunked active GEMMs (typical: 1 chunk of <=16) ----
    const int nch = (K + CH - 1) / CH;
    for (int ac = 0; ac < nch; ++ac) {
        const int an0 = ac * CH;
        int cn = K - an0; if (cn > CH) cn = CH;

        __syncthreads();   // protect prior readers of sSa / sQ
        // build Sa[i][a] = md_i*inv_i*(adj[i][ja]+delta)*di_ja*ca_ja  (pad 0)
        if (tid < NN) {
            const int i = tid;
            const float mi = s_md[i] * s_iv[i];
            #pragma unroll
            for (int a = 0; a < CH; ++a) {
                float v = 0.0f;
                if (a < cn) {
                    int ja = s_ac[an0 + a];
                    v = mi * (sA[i*AST + ja] + ((i == ja) ? 1.0f : 0.0f))
                           * (s_di[ja] * s_ca[ja]);
                }
                sSa[i*SST + a] = v;
            }
        }
        __syncthreads();

        // GEMM2': Qa[a][m] = sum_i Sa[i][a] * adj[i][m]   (128 threads, m = tid)
        if (tid < NN) {
            const int m = tid;
            float acc[CH];
            #pragma unroll
            for (int a = 0; a < CH; ++a) acc[a] = 0.0f;
            #pragma unroll 2
            for (int i = 0; i < NN; ++i) {
                const float av = sA[i*AST + m];
                const float4 w0 = *reinterpret_cast<float4*>(&sSa[i*SST + 0]);
                const float4 w1 = *reinterpret_cast<float4*>(&sSa[i*SST + 4]);
                const float4 w2 = *reinterpret_cast<float4*>(&sSa[i*SST + 8]);
                const float4 w3 = *reinterpret_cast<float4*>(&sSa[i*SST + 12]);
                acc[0]  = fmaf(w0.x, av, acc[0]);  acc[1]  = fmaf(w0.y, av, acc[1]);
                acc[2]  = fmaf(w0.z, av, acc[2]);  acc[3]  = fmaf(w0.w, av, acc[3]);
                acc[4]  = fmaf(w1.x, av, acc[4]);  acc[5]  = fmaf(w1.y, av, acc[5]);
                acc[6]  = fmaf(w1.z, av, acc[6]);  acc[7]  = fmaf(w1.w, av, acc[7]);
                acc[8]  = fmaf(w2.x, av, acc[8]);  acc[9]  = fmaf(w2.y, av, acc[9]);
                acc[10] = fmaf(w2.z, av, acc[10]); acc[11] = fmaf(w2.w, av, acc[11]);
                acc[12] = fmaf(w3.x, av, acc[12]); acc[13] = fmaf(w3.y, av, acc[13]);
                acc[14] = fmaf(w3.z, av, acc[14]); acc[15] = fmaf(w3.w, av, acc[15]);
            }
            #pragma unroll
            for (int a = 0; a < CH; ++a)
                if (a < cn) sQ[a*AST + m] = acc[a];
        }

        // GEMM1': emb[ja][d] = sum_i Sa[i][a] * x[i][d]   (256 threads, d = tid)
        {
            const int d = tid;
            float acc[CH];
            #pragma unroll
            for (int a = 0; a < CH; ++a) acc[a] = 0.0f;
            #pragma unroll 2
            for (int i = 0; i < NN; ++i) {
                const float xv = xB[(size_t)i * DD + d];
                const float4 w0 = *reinterpret_cast<float4*>(&sSa[i*SST + 0]);
                const float4 w1 = *reinterpret_cast<float4*>(&sSa[i*SST + 4]);
                const float4 w2 = *reinterpret_cast<float4*>(&sSa[i*SST + 8]);
                const float4 w3 = *reinterpret_cast<float4*>(&sSa[i*SST + 12]);
                acc[0]  = fmaf(w0.x, xv, acc[0]);  acc[1]  = fmaf(w0.y, xv, acc[1]);
                acc[2]  = fmaf(w0.z, xv, acc[2]);  acc[3]  = fmaf(w0.w, xv, acc[3]);
                acc[4]  = fmaf(w1.x, xv, acc[4]);  acc[5]  = fmaf(w1.y, xv, acc[5]);
                acc[6]  = fmaf(w1.z, xv, acc[6]);  acc[7]  = fmaf(w1.w, xv, acc[7]);
                acc[8]  = fmaf(w2.x, xv, acc[8]);  acc[9]  = fmaf(w2.y, xv, acc[9]);
                acc[10] = fmaf(w2.z, xv, acc[10]); acc[11] = fmaf(w2.w, xv, acc[11]);
                acc[12] = fmaf(w3.x, xv, acc[12]); acc[13] = fmaf(w3.y, xv, acc[13]);
                acc[14] = fmaf(w3.z, xv, acc[14]); acc[15] = fmaf(w3.w, xv, acc[15]);
            }
            #pragma unroll
            for (int a = 0; a < CH; ++a)
                if (a < cn) oE[(size_t)s_ac[an0 + a] * DD + d] = acc[a];
        }
        __syncthreads();   // sQ ready

        // GEMM3': new_adj[ja][jb] = sum_m Qa[a][m] * Sb[m][b]
        for (int bc = 0; bc < nch; ++bc) {
            const int bn0 = bc * CH;
            int bn = K - bn0; if (bn > CH) bn = CH;

            __syncthreads();   // protect prior readers of sSb
            if (tid < NN) {
                const int i = tid;
                const float mi = s_md[i] * s_iv[i];
                #pragma unroll
                for (int bq = 0; bq < CH; ++bq) {
                    float v = 0.0f;
                    if (bq < bn) {
                        int jb = s_ac[bn0 + bq];
                        v = mi * (sA[i*AST + jb] + ((i == jb) ? 1.0f : 0.0f))
                               * (s_di[jb] * s_ca[jb]);
                    }
                    sSb[i*SST + bq] = v;
                }
            }
            __syncthreads();

            {
                const int a  = tid >> 4;
                const int bq = tid & 15;
                float v = 0.0f;
                #pragma unroll 4
                for (int m = 0; m < NN; ++m)
                    v = fmaf(sQ[a*AST + m], sSb[m*SST + bq], v);
                if (a < cn && bq < bn)
                    oA[(size_t)s_ac[an0 + a] * NN + s_ac[bn0 + bq]] = v;
            }
        }
    }
}

extern "C" void kernel_launch(void* const* d_in, const int* in_sizes, int n_in,
                              void* d_out, int out_size)
{
    const float* x    = (const float*)d_in[0];   // [B,128,256]
    const float* adj  = (const float*)d_in[1];   // [B,128,128]
    const int*   head = (const int*)  d_in[2];   // [B,512]
    const float* lw   = (const float*)d_in[3];   // [1,256]
    const float* bs   = (const float*)d_in[4];   // [1]

    const int B = in_sizes[0] / (NN * DD);       // 512

    float* out_emb = (float*)d_out;                       // [B,128,256]
    float* out_adj = out_emb + (size_t)B * NN * DD;       // [B,128,128]

    cudaFuncSetAttribute(graph_enc_kernel,
                         cudaFuncAttributeMaxDynamicSharedMemorySize, SMEM_BYTES);
    graph_enc_kernel<<<B, THREADS, SMEM_BYTES>>>(x, adj, head, lw, bs, out_emb, out_adj);
}